// round 16
// baseline (speedup 1.0000x reference)
#include <cuda_runtime.h>
#include <cuda_fp16.h>
#include <math.h>
#include <stdint.h>

#define SEQ   512
#define BATCH 128
#define DIN   512
#define HDIM  512
#define G3    1536
#define MROWS (SEQ * BATCH)        // 65536

// ---------------- scratch (device globals) ----------------
__device__ __half g_ins16[(size_t)MROWS * DIN];              // ins fp16 [s*128+b][k] (67MB)
__device__ __half g_Wcat[(size_t)32 * 48 * 1024];            // [by][c][k]: k<512 W_in^T, k>=512 W_h^T
__device__ __half g_h16[2][(size_t)BATCH * HDIM];            // [parity][b*512+hh]
__device__ int      g_reset_mode;
__device__ unsigned g_done[SEQ * 4];                         // per-(step,bx) counters

// ---------------- mma.sync helpers ----------------
__device__ __forceinline__ uint32_t smem_u32(const void* p) {
    return (uint32_t)__cvta_generic_to_shared(p);
}
__device__ __forceinline__ void ldsm4(uint32_t* r, uint32_t addr) {
    asm volatile("ldmatrix.sync.aligned.m8n8.x4.shared.b16 {%0,%1,%2,%3}, [%4];"
                 : "=r"(r[0]), "=r"(r[1]), "=r"(r[2]), "=r"(r[3]) : "r"(addr));
}
__device__ __forceinline__ void mma16816(float* c, const uint32_t* a,
                                         uint32_t b0, uint32_t b1) {
    asm volatile(
        "mma.sync.aligned.m16n8k16.row.col.f32.f16.f16.f32 "
        "{%0,%1,%2,%3}, {%4,%5,%6,%7}, {%8,%9}, {%0,%1,%2,%3};"
        : "+f"(c[0]), "+f"(c[1]), "+f"(c[2]), "+f"(c[3])
        : "r"(a[0]), "r"(a[1]), "r"(a[2]), "r"(a[3]), "r"(b0), "r"(b1));
}
__device__ __forceinline__ unsigned ld_acq(const unsigned* p) {
    unsigned v;
    asm volatile("ld.acquire.gpu.global.u32 %0, [%1];" : "=r"(v) : "l"(p) : "memory");
    return v;
}
__device__ __forceinline__ void red_rel(unsigned* p) {
    asm volatile("red.release.gpu.global.add.u32 [%0], 1;" :: "l"(p) : "memory");
}
__device__ __forceinline__ uint32_t pack2h(__half a, __half b) {
    __half2 v; v.x = a; v.y = b;
    return *(uint32_t*)&v;
}

// ---------------- init + reset dtype sniffing ----------------
__global__ void init_kernel(const unsigned int* __restrict__ r) {
    int t = blockIdx.x * 256 + threadIdx.x;
    for (int i = t; i < SEQ * 4; i += 512) g_done[i] = 0u;
    if (t == 0) {
        bool word_mode = true;
        for (int i = 0; i < 64; i++) {
            unsigned v = r[i];
            if (!(v == 0u || v == 1u || v == 0x3F800000u)) { word_mode = false; break; }
        }
        g_reset_mode = word_mode ? 0 : 2;
    }
}

// ---------------- prep kernels ----------------
__global__ void prep_ins_kernel(const float* __restrict__ ins) {
    size_t base = ((size_t)blockIdx.x * 256 + threadIdx.x) * 4;
    if (base < (size_t)MROWS * DIN) {
        float4 v = *(const float4*)(ins + base);
        uint2 hv;
        hv.x = pack2h(__float2half(v.x), __float2half(v.y));
        hv.y = pack2h(__float2half(v.z), __float2half(v.w));
        *(uint2*)&g_ins16[base] = hv;
    }
}
// W_cat: [by][c(0..47)][k 0..1023]; c: j = c>>4 gate, hh = by*16 + (c&15)
// k<512: W_in[k][j*512+hh]; k>=512: W_h[k-512][j*512+hh]
__global__ void prep_wcat_kernel(const float* __restrict__ Win,
                                 const float* __restrict__ Wh) {
    int idx = blockIdx.x * 256 + threadIdx.x;   // over 32*48*1024
    if (idx < 32 * 48 * 1024) {
        int k  = idx & 1023;
        int c  = (idx >> 10) % 48;
        int by = idx / (48 * 1024);
        int jmap = (c >> 4) * HDIM + by * 16 + (c & 15);
        float x = (k < 512) ? Win[(size_t)k * G3 + jmap]
                            : Wh[(size_t)(k - 512) * G3 + jmap];
        g_Wcat[idx] = __float2half(x);
    }
}

// ---------------- fused persistent scan (gates gemm folded in) ----------------
// 128 blocks (bx=bid&3: 32 batches; by=bid>>2: 16 hh), 512 threads, 16 warps.
// Per step: C[32b][48c] = [ins_s | h] (32x1024) @ W_cat^T.
// Warps 0-7: ins half (k 0..511)  — runs during the h-wait.
// Warps 8-15: h half (k 512..1023) — wait, stage, mma.
// Epilogue keeps ins-n and h-n partials SEPARATE: n = tanh(b_n + n_in + r*n_h).
// Smem: A 32x2064 (row = [ins 1024B | h 1024B]); W 48x2064; red 16x768 fp32.
#define AROW     2064
#define W_OFF    66048            // 32*2064
#define RED_OFF  165120           // + 48*2064
#define SCAN_SMEM 214272          // + 16*768*4

__global__ __launch_bounds__(512)
void scan_mma_kernel(const float* __restrict__ carry,
                     const void*  __restrict__ resets,
                     const float* __restrict__ b_in,
                     float* __restrict__ outputs,
                     float* __restrict__ carry_out) {
    extern __shared__ char smem[];
    uint32_t sbase = smem_u32(smem);

    int t = threadIdx.x, l = t & 31, wid = t >> 5;
    int mw = (wid >> 2) & 1;
    uint32_t kwbase = (uint32_t)((wid & 3) * 256 + ((wid >= 8) ? 1024 : 0));
    int bid = blockIdx.x;
    int bx = bid & 3, by = bid >> 2;
    int b0 = bx * 32;
    int hh0g = by * 16;
    int mode = g_reset_mode;

    const unsigned char* rbytes = (const unsigned char*)resets;
    const int*           rints  = (const int*)resets;

    // ---- one-time: W_cat slice into smem (48 rows x 2048B) ----
    {
        const char* wg = (const char*)g_Wcat + (size_t)by * 48 * 1024 * 2;
#pragma unroll
        for (int i = 0; i < 12; i++) {
            int u = t + i * 512;                 // 6144 units of 16B
            int row = u >> 7, off = (u & 127) * 16;
            *(uint4*)(smem + W_OFF + row * AROW + off) =
                *(const uint4*)(wg + (size_t)row * 2048 + off);
        }
    }

    uint32_t aoff = sbase +
        (uint32_t)((mw * 16 + (l & 7) + ((l >> 3) & 1) * 8) * AROW + ((l >> 4) * 8) * 2);
    uint32_t boff = sbase + W_OFF +
        (uint32_t)(((l & 7) + ((l >> 4) * 8)) * AROW + (((l >> 3) & 1) * 8) * 2);

    // staging identity (within each 256-thread group): row = g>>3, seg = g&7 (128B)
    int g256 = t & 255;
    int srow = g256 >> 3, sseg = g256 & 7;

    // epilogue identity: 1 value per thread
    int eb = t >> 4, ehh = t & 15;
    int gb = b0 + eb;
    int ghh = hh0g + ehh;
    int emw = eb >> 4, erow8 = (eb >> 3) & 1, erowl = eb & 7;
    int nt01 = ehh >> 3;
    int elane = erowl * 4 + ((ehh & 7) >> 1);
    int ecreg = erow8 * 2 + (ehh & 1);

    float hp = carry[(size_t)gb * HDIM + ghh];
    float bz = b_in[ghh];
    float br = b_in[HDIM + ghh];
    float bnn = b_in[2 * HDIM + ghh];

    float* redf = (float*)(smem + RED_OFF);
    __syncthreads();   // W staged

    for (int s = 0; s < SEQ; s++) {
        int par = s & 1;

        bool ers = (mode == 0) ? (rints[s * BATCH + gb] != 0)
                               : (rbytes[s * BATCH + gb] != 0);
        float em = ers ? 0.f : 1.f;

        float acc[6][4];
#pragma unroll
        for (int i = 0; i < 6; i++)
#pragma unroll
            for (int j = 0; j < 4; j++) acc[i][j] = 0.f;

        if (wid < 8) {
            // ---- ins half: stage ins[s] slice, barrier 1, mma ----
            {
                char* dst = smem + srow * AROW + sseg * 128;
                const char* src = (const char*)&g_ins16[((size_t)s * BATCH + b0 + srow) * DIN]
                                  + sseg * 128;
#pragma unroll
                for (int i = 0; i < 8; i++)
                    *(uint4*)(dst + i * 16) = *(const uint4*)(src + i * 16);
            }
            asm volatile("bar.sync 1, 256;" ::: "memory");
        } else {
            // ---- h half: wait for prev step, stage h (masked), barrier 2, mma ----
            if (s > 0) {
                if (l == 0) {
                    unsigned* cp = &g_done[(s - 1) * 4 + bx];
                    while (ld_acq(cp) < 32u) { }
                }
                __syncwarp();
            }
            bool srs = (mode == 0) ? (rints[s * BATCH + b0 + srow] != 0)
                                   : (rbytes[s * BATCH + b0 + srow] != 0);
            {
                char* dst = smem + srow * AROW + 1024 + sseg * 128;
                if (srs) {
                    uint4 z = make_uint4(0, 0, 0, 0);
#pragma unroll
                    for (int i = 0; i < 8; i++) *(uint4*)(dst + i * 16) = z;
                } else if (s == 0) {
                    const float* cp = carry + (size_t)(b0 + srow) * HDIM + sseg * 64;
#pragma unroll
                    for (int i = 0; i < 8; i++) {
                        float4 v0 = *(const float4*)(cp + i * 8);
                        float4 v1 = *(const float4*)(cp + i * 8 + 4);
                        uint4 hv;
                        hv.x = pack2h(__float2half(v0.x), __float2half(v0.y));
                        hv.y = pack2h(__float2half(v0.z), __float2half(v0.w));
                        hv.z = pack2h(__float2half(v1.x), __float2half(v1.y));
                        hv.w = pack2h(__float2half(v1.z), __float2half(v1.w));
                        *(uint4*)(dst + i * 16) = hv;
                    }
                } else {
                    const char* src = (const char*)&g_h16[par][(size_t)(b0 + srow) * HDIM]
                                      + sseg * 128;
#pragma unroll
                    for (int i = 0; i < 8; i++)
                        *(uint4*)(dst + i * 16) = *(const uint4*)(src + i * 16);
                }
            }
            asm volatile("bar.sync 2, 256;" ::: "memory");
        }

        // ---- mma over this warp's 128-k (256B) window ----
#pragma unroll
        for (int kt = 0; kt < 8; kt++) {
            uint32_t kb = kwbase + (uint32_t)(kt * 32);
            uint32_t fah[4], fbh[3][4];
            ldsm4(fah, aoff + kb);
#pragma unroll
            for (int j2 = 0; j2 < 3; j2++)
                ldsm4(fbh[j2], boff + j2 * (16 * AROW) + kb);
#pragma unroll
            for (int j2 = 0; j2 < 3; j2++)
#pragma unroll
                for (int sub = 0; sub < 2; sub++) {
                    int nt = j2 * 2 + sub;
                    mma16816(acc[nt], fah, fbh[j2][sub * 2], fbh[j2][sub * 2 + 1]);
                }
        }

        // ---- store partials ----
        {
            float* rw = redf + wid * 768;
#pragma unroll
            for (int nt = 0; nt < 6; nt++)
#pragma unroll
                for (int c = 0; c < 4; c++)
                    rw[(nt * 4 + c) * 32 + l] = acc[nt][c];
        }
        __syncthreads();

        // ---- epilogue: 1 h value per thread; n-gate keeps ins/h parts separate ----
        float sz = 0.f, sr = 0.f, sni = 0.f, snh = 0.f;
#pragma unroll
        for (int kwp = 0; kwp < 8; kwp++) {
            int w = emw * 4 + (kwp & 3) + ((kwp & 4) << 1);
            const float* rb = redf + w * 768;
            sz += rb[((0 * 2 + nt01) * 4 + ecreg) * 32 + elane];
            sr += rb[((1 * 2 + nt01) * 4 + ecreg) * 32 + elane];
            float nv = rb[((2 * 2 + nt01) * 4 + ecreg) * 32 + elane];
            if (kwp < 4) sni += nv;   // ins windows (warps 0-7): n_in part
            else         snh += nv;   // h windows (warps 8-15): n_h part
        }
        float z = 1.f / (1.f + __expf(-(bz + sz)));
        float r = 1.f / (1.f + __expf(-(br + sr)));
        float n = tanhf(bnn + sni + r * snh);
        float hn = (1.f - z) * n + z * (hp * em);
        hp = hn;

        outputs[((size_t)s * BATCH + gb) * HDIM + ghh] = hn;
        g_h16[par ^ 1][(size_t)gb * HDIM + ghh] = __float2half(hn);
        if (carry_out && s == SEQ - 1)
            carry_out[(size_t)gb * HDIM + ghh] = hn;

        __syncthreads();
        if (t == 0 && s < SEQ - 1) red_rel(&g_done[s * 4 + bx]);
    }
}

// ---------------- launcher ----------------
extern "C" void kernel_launch(void* const* d_in, const int* in_sizes, int n_in,
                              void* d_out, int out_size) {
    const float* carry = (const float*)d_in[0];
    const float* ins   = (const float*)d_in[1];
    const void*  rsts  = d_in[2];
    const float* W_in  = (const float*)d_in[3];
    const float* b_in  = (const float*)d_in[4];
    const float* W_h   = (const float*)d_in[5];

    float* out = (float*)d_out;
    float* carry_out;
    float* outputs;
    if (out_size == (int)((size_t)SEQ * BATCH * HDIM)) {
        carry_out = nullptr;
        outputs   = out;
    } else {
        carry_out = out;
        outputs   = out + (size_t)BATCH * HDIM;
    }

    cudaFuncSetAttribute(scan_mma_kernel,
                         cudaFuncAttributeMaxDynamicSharedMemorySize, SCAN_SMEM);

    init_kernel<<<2, 256>>>((const unsigned int*)rsts);
    prep_ins_kernel<<<(int)(((size_t)MROWS * DIN / 4 + 255) / 256), 256>>>(ins);
    prep_wcat_kernel<<<(32 * 48 * 1024 + 255) / 256, 256>>>(W_in, W_h);
    scan_mma_kernel<<<128, 512, SCAN_SMEM>>>(carry, rsts, b_in, outputs, carry_out);
}

// round 17
// speedup vs baseline: 1.0097x; 1.0097x over previous
#include <cuda_runtime.h>
#include <cuda_fp16.h>
#include <math.h>
#include <stdint.h>

#define SEQ   512
#define BATCH 128
#define DIN   512
#define HDIM  512
#define G3    1536
#define MROWS (SEQ * BATCH)        // 65536

// ---------------- scratch (device globals) ----------------
__device__ __half g_ins16[(size_t)MROWS * DIN];              // ins fp16 [s*128+b][k] (67MB)
__device__ __half g_Wcat[(size_t)32 * 48 * 1024];            // [by][c][k]: k<512 W_in^T, k>=512 W_h^T
__device__ __half g_h16[2][(size_t)BATCH * HDIM];            // [parity][b*512+hh]
__device__ int      g_reset_mode;
__device__ unsigned g_done[SEQ * 4];                         // per-(step,bx) counters

// ---------------- mma.sync helpers ----------------
__device__ __forceinline__ uint32_t smem_u32(const void* p) {
    return (uint32_t)__cvta_generic_to_shared(p);
}
__device__ __forceinline__ void ldsm4(uint32_t* r, uint32_t addr) {
    asm volatile("ldmatrix.sync.aligned.m8n8.x4.shared.b16 {%0,%1,%2,%3}, [%4];"
                 : "=r"(r[0]), "=r"(r[1]), "=r"(r[2]), "=r"(r[3]) : "r"(addr));
}
__device__ __forceinline__ void mma16816(float* c, const uint32_t* a,
                                         uint32_t b0, uint32_t b1) {
    asm volatile(
        "mma.sync.aligned.m16n8k16.row.col.f32.f16.f16.f32 "
        "{%0,%1,%2,%3}, {%4,%5,%6,%7}, {%8,%9}, {%0,%1,%2,%3};"
        : "+f"(c[0]), "+f"(c[1]), "+f"(c[2]), "+f"(c[3])
        : "r"(a[0]), "r"(a[1]), "r"(a[2]), "r"(a[3]), "r"(b0), "r"(b1));
}
__device__ __forceinline__ unsigned ld_acq(const unsigned* p) {
    unsigned v;
    asm volatile("ld.acquire.gpu.global.u32 %0, [%1];" : "=r"(v) : "l"(p) : "memory");
    return v;
}
__device__ __forceinline__ void red_rel(unsigned* p) {
    asm volatile("red.release.gpu.global.add.u32 [%0], 1;" :: "l"(p) : "memory");
}
__device__ __forceinline__ uint32_t pack2h(__half a, __half b) {
    __half2 v; v.x = a; v.y = b;
    return *(uint32_t*)&v;
}

// ---------------- init + reset dtype sniffing ----------------
__global__ void init_kernel(const unsigned int* __restrict__ r) {
    int t = blockIdx.x * 256 + threadIdx.x;
    for (int i = t; i < SEQ * 4; i += 512) g_done[i] = 0u;
    if (t == 0) {
        bool word_mode = true;
        for (int i = 0; i < 64; i++) {
            unsigned v = r[i];
            if (!(v == 0u || v == 1u || v == 0x3F800000u)) { word_mode = false; break; }
        }
        g_reset_mode = word_mode ? 0 : 2;
    }
}

// ---------------- prep kernels ----------------
__global__ void prep_ins_kernel(const float* __restrict__ ins) {
    size_t base = ((size_t)blockIdx.x * 256 + threadIdx.x) * 4;
    if (base < (size_t)MROWS * DIN) {
        float4 v = *(const float4*)(ins + base);
        uint2 hv;
        hv.x = pack2h(__float2half(v.x), __float2half(v.y));
        hv.y = pack2h(__float2half(v.z), __float2half(v.w));
        *(uint2*)&g_ins16[base] = hv;
    }
}
// W_cat: [by][c(0..47)][k 0..1023]; c: j = c>>4 gate, hh = by*16 + (c&15)
__global__ void prep_wcat_kernel(const float* __restrict__ Win,
                                 const float* __restrict__ Wh) {
    int idx = blockIdx.x * 256 + threadIdx.x;   // over 32*48*1024
    if (idx < 32 * 48 * 1024) {
        int k  = idx & 1023;
        int c  = (idx >> 10) % 48;
        int by = idx / (48 * 1024);
        int jmap = (c >> 4) * HDIM + by * 16 + (c & 15);
        float x = (k < 512) ? Win[(size_t)k * G3 + jmap]
                            : Wh[(size_t)(k - 512) * G3 + jmap];
        g_Wcat[idx] = __float2half(x);
    }
}

// ---------------- fused persistent scan (register-prefetched ins) ----------------
// 128 blocks (bx=bid&3: 32 batches; by=bid>>2: 16 hh), 512 threads, 16 warps.
// Per step: C[32b][48c] = [ins_s | h] (32x1024) @ W_cat^T, n-gate parts kept separate.
// Warps 0-7: ins half — STS prefetched regs, mma; prefetch ins(s+1) after mma.
// Warps 8-15: h half — wait, stage (L2-hit), mma.
// Smem: I 32x1040 | H 32x1040 | W 48x2064 ([Win|Wh] rows) | red 16x768 fp32.
#define IROW     1040
#define AROW     2064
#define I_OFF    0
#define H_OFF    33280
#define W_OFF    66560            // + 32*1040
#define RED_OFF  165632           // + 48*2064
#define SCAN_SMEM (RED_OFF + 16 * 768 * 4)   // 214784

__global__ __launch_bounds__(512)
void scan_mma_kernel(const float* __restrict__ carry,
                     const void*  __restrict__ resets,
                     const float* __restrict__ b_in,
                     float* __restrict__ outputs,
                     float* __restrict__ carry_out) {
    extern __shared__ char smem[];
    uint32_t sbase = smem_u32(smem);

    int t = threadIdx.x, l = t & 31, wid = t >> 5;
    int mw = (wid >> 2) & 1;
    bool is_h = (wid >= 8);
    uint32_t kwA = (uint32_t)((wid & 3) * 256);                      // A-side window (bytes)
    uint32_t kwB = kwA + (is_h ? 1024u : 0u);                        // B-side window (bytes)
    int bid = blockIdx.x;
    int bx = bid & 3, by = bid >> 2;
    int b0 = bx * 32;
    int hh0g = by * 16;
    int mode = g_reset_mode;

    const unsigned char* rbytes = (const unsigned char*)resets;
    const int*           rints  = (const int*)resets;

    // ---- one-time: W_cat slice into smem (48 rows x 2048B, pitch 2064) ----
    {
        const char* wg = (const char*)g_Wcat + (size_t)by * 48 * 1024 * 2;
#pragma unroll
        for (int i = 0; i < 12; i++) {
            int u = t + i * 512;                 // 6144 units of 16B
            int row = u >> 7, off = (u & 127) * 16;
            *(uint4*)(smem + W_OFF + row * AROW + off) =
                *(const uint4*)(wg + (size_t)row * 2048 + off);
        }
    }

    uint32_t aoff = sbase + (is_h ? H_OFF : I_OFF) +
        (uint32_t)((mw * 16 + (l & 7) + ((l >> 3) & 1) * 8) * IROW + ((l >> 4) * 8) * 2);
    uint32_t boff = sbase + W_OFF +
        (uint32_t)(((l & 7) + ((l >> 4) * 8)) * AROW + (((l >> 3) & 1) * 8) * 2);

    // staging identity (within each 256-thread group): row = g>>3, seg = g&7 (128B)
    int g256 = t & 255;
    int srow = g256 >> 3, sseg = g256 & 7;

    // epilogue identity: 1 value per thread
    int eb = t >> 4, ehh = t & 15;
    int gb = b0 + eb;
    int ghh = hh0g + ehh;
    int emw = eb >> 4, erow8 = (eb >> 3) & 1, erowl = eb & 7;
    int nt01 = ehh >> 3;
    int elane = erowl * 4 + ((ehh & 7) >> 1);
    int ecreg = erow8 * 2 + (ehh & 1);

    float hp = carry[(size_t)gb * HDIM + ghh];
    float bz = b_in[ghh];
    float br = b_in[HDIM + ghh];
    float bnn = b_in[2 * HDIM + ghh];

    float* redf = (float*)(smem + RED_OFF);

    // ---- ins register prefetch (warps 0-7): step 0 ----
    uint4 pin[8];
    const char* ins_src = (const char*)&g_ins16[((size_t)0 * BATCH + b0 + srow) * DIN]
                          + sseg * 128;
    if (!is_h) {
#pragma unroll
        for (int i = 0; i < 8; i++) pin[i] = *(const uint4*)(ins_src + i * 16);
    }

    __syncthreads();   // W staged

    for (int s = 0; s < SEQ; s++) {
        int par = s & 1;

        bool ers = (mode == 0) ? (rints[s * BATCH + gb] != 0)
                               : (rbytes[s * BATCH + gb] != 0);
        float em = ers ? 0.f : 1.f;

        float acc[6][4];
#pragma unroll
        for (int i = 0; i < 6; i++)
#pragma unroll
            for (int j = 0; j < 4; j++) acc[i][j] = 0.f;

        if (!is_h) {
            // ---- ins half: STS prefetched regs, barrier 1 ----
            {
                char* dst = smem + I_OFF + srow * IROW + sseg * 128;
#pragma unroll
                for (int i = 0; i < 8; i++) *(uint4*)(dst + i * 16) = pin[i];
            }
            asm volatile("bar.sync 1, 256;" ::: "memory");
        } else {
            // ---- h half: wait for prev step, stage h (masked), barrier 2 ----
            if (s > 0) {
                if (l == 0) {
                    unsigned* cp = &g_done[(s - 1) * 4 + bx];
                    while (ld_acq(cp) < 32u) { }
                }
                __syncwarp();
            }
            bool srs = (mode == 0) ? (rints[s * BATCH + b0 + srow] != 0)
                                   : (rbytes[s * BATCH + b0 + srow] != 0);
            {
                char* dst = smem + H_OFF + srow * IROW + sseg * 128;
                if (srs) {
                    uint4 z = make_uint4(0, 0, 0, 0);
#pragma unroll
                    for (int i = 0; i < 8; i++) *(uint4*)(dst + i * 16) = z;
                } else if (s == 0) {
                    const float* cp = carry + (size_t)(b0 + srow) * HDIM + sseg * 64;
#pragma unroll
                    for (int i = 0; i < 8; i++) {
                        float4 v0 = *(const float4*)(cp + i * 8);
                        float4 v1 = *(const float4*)(cp + i * 8 + 4);
                        uint4 hv;
                        hv.x = pack2h(__float2half(v0.x), __float2half(v0.y));
                        hv.y = pack2h(__float2half(v0.z), __float2half(v0.w));
                        hv.z = pack2h(__float2half(v1.x), __float2half(v1.y));
                        hv.w = pack2h(__float2half(v1.z), __float2half(v1.w));
                        *(uint4*)(dst + i * 16) = hv;
                    }
                } else {
                    const char* src = (const char*)&g_h16[par][(size_t)(b0 + srow) * HDIM]
                                      + sseg * 128;
#pragma unroll
                    for (int i = 0; i < 8; i++)
                        *(uint4*)(dst + i * 16) = *(const uint4*)(src + i * 16);
                }
            }
            asm volatile("bar.sync 2, 256;" ::: "memory");
        }

        // ---- mma over this warp's 128-k (256B) window ----
#pragma unroll
        for (int kt = 0; kt < 8; kt++) {
            uint32_t kab = kwA + (uint32_t)(kt * 32);
            uint32_t kbb = kwB + (uint32_t)(kt * 32);
            uint32_t fah[4], fbh[3][4];
            ldsm4(fah, aoff + kab);
#pragma unroll
            for (int j2 = 0; j2 < 3; j2++)
                ldsm4(fbh[j2], boff + j2 * (16 * AROW) + kbb);
#pragma unroll
            for (int j2 = 0; j2 < 3; j2++)
#pragma unroll
                for (int sub = 0; sub < 2; sub++) {
                    int nt = j2 * 2 + sub;
                    mma16816(acc[nt], fah, fbh[j2][sub * 2], fbh[j2][sub * 2 + 1]);
                }
        }

        // ---- prefetch ins(s+1) into regs (warps 0-7); hides DRAM under epilogue ----
        if (!is_h && s + 1 < SEQ) {
            const char* src = ins_src + (size_t)(s + 1) * BATCH * DIN * 2;
#pragma unroll
            for (int i = 0; i < 8; i++) pin[i] = *(const uint4*)(src + i * 16);
        }

        // ---- store partials ----
        {
            float* rw = redf + wid * 768;
#pragma unroll
            for (int nt = 0; nt < 6; nt++)
#pragma unroll
                for (int c = 0; c < 4; c++)
                    rw[(nt * 4 + c) * 32 + l] = acc[nt][c];
        }
        __syncthreads();

        // ---- epilogue: 1 h value per thread; n-gate parts separate ----
        float sz = 0.f, sr = 0.f, sni = 0.f, snh = 0.f;
#pragma unroll
        for (int kwp = 0; kwp < 8; kwp++) {
            int w = emw * 4 + (kwp & 3) + ((kwp & 4) << 1);
            const float* rb = redf + w * 768;
            sz += rb[((0 * 2 + nt01) * 4 + ecreg) * 32 + elane];
            sr += rb[((1 * 2 + nt01) * 4 + ecreg) * 32 + elane];
            float nv = rb[((2 * 2 + nt01) * 4 + ecreg) * 32 + elane];
            if (kwp < 4) sni += nv;   // ins windows (warps 0-7)
            else         snh += nv;   // h windows (warps 8-15)
        }
        float z = 1.f / (1.f + __expf(-(bz + sz)));
        float r = 1.f / (1.f + __expf(-(br + sr)));
        float n = tanhf(bnn + sni + r * snh);
        float hn = (1.f - z) * n + z * (hp * em);
        hp = hn;

        outputs[((size_t)s * BATCH + gb) * HDIM + ghh] = hn;
        g_h16[par ^ 1][(size_t)gb * HDIM + ghh] = __float2half(hn);
        if (carry_out && s == SEQ - 1)
            carry_out[(size_t)gb * HDIM + ghh] = hn;

        __syncthreads();
        if (t == 0 && s < SEQ - 1) red_rel(&g_done[s * 4 + bx]);
    }
}

// ---------------- launcher ----------------
extern "C" void kernel_launch(void* const* d_in, const int* in_sizes, int n_in,
                              void* d_out, int out_size) {
    const float* carry = (const float*)d_in[0];
    const float* ins   = (const float*)d_in[1];
    const void*  rsts  = d_in[2];
    const float* W_in  = (const float*)d_in[3];
    const float* b_in  = (const float*)d_in[4];
    const float* W_h   = (const float*)d_in[5];

    float* out = (float*)d_out;
    float* carry_out;
    float* outputs;
    if (out_size == (int)((size_t)SEQ * BATCH * HDIM)) {
        carry_out = nullptr;
        outputs   = out;
    } else {
        carry_out = out;
        outputs   = out + (size_t)BATCH * HDIM;
    }

    cudaFuncSetAttribute(scan_mma_kernel,
                         cudaFuncAttributeMaxDynamicSharedMemorySize, SCAN_SMEM);

    init_kernel<<<2, 256>>>((const unsigned int*)rsts);
    prep_ins_kernel<<<(int)(((size_t)MROWS * DIN / 4 + 255) / 256), 256>>>(ins);
    prep_wcat_kernel<<<(32 * 48 * 1024 + 255) / 256, 256>>>(W_in, W_h);
    scan_mma_kernel<<<128, 512, SCAN_SMEM>>>(carry, rsts, b_in, outputs, carry_out);
}